// round 16
// baseline (speedup 1.0000x reference)
#include <cuda_runtime.h>
#include <cuda_fp16.h>
#include <cstdint>

// ---------------- problem constants ----------------
#define BB    2
#define TT    2048
#define DD    1024
#define HH    4
#define KDIM  512            // KD = H*DK
#define VDIM  1024           // VD = H*DV
#define DK    128
#define DV    256
#define CHUNK 64
#define NC    32             // T / CHUNK
#define BT    4096           // B*T
#define LR    16             // LOW_RANK
#define SCALE 0.088388347648318447f   // DK^-0.5
#define EPSN  1e-6f

// ---------------- scratch (no allocations allowed) ----------------
__device__ float  g_q  [BT * KDIM];       // qg fp32 (for scan)
__device__ float  g_k  [BT * KDIM];       // kg fp32 (for scan)
__device__ float  g_G  [BT * KDIM];       // cumsum'd gate
__device__ float  g_v  [BT * VDIM];       // v fp32 (for scan)
__device__ float  g_g  [BT * VDIM];
__device__ float  g_o  [BT * VDIM];
__device__ __half g_xh [BT * DD];         // x in fp16
__device__ __half g_WTh[3072 * DD];       // [Wq;Wk;Wv;Wg]^T, K-major, fp16
__device__ __half g_WoTh[DD * VDIM];      // Wo^T, K-major, fp16
__device__ __half g_oh [BT * VDIM];       // norm-gated o in fp16
__device__ __half g_qh [BT * KDIM];       // qg fp16 (for intra)
__device__ __half g_kh [BT * KDIM];       // kg fp16 (for intra)
__device__ __half g_vh [BT * VDIM];       // v  fp16 (for intra)

// =====================================================================
// PTX helpers
// =====================================================================
__device__ __forceinline__ uint32_t smem_u32(const void* p) {
    uint32_t a;
    asm("{ .reg .u64 t; cvta.to.shared.u64 t, %1; cvt.u32.u64 %0, t; }" : "=r"(a) : "l"(p));
    return a;
}
__device__ __forceinline__ void cp16(uint32_t saddr, const void* gaddr) {
    asm volatile("cp.async.ca.shared.global [%0], [%1], 16;" :: "r"(saddr), "l"(gaddr));
}
__device__ __forceinline__ void cp_commit() {
    asm volatile("cp.async.commit_group;" ::: "memory");
}
template <int N>
__device__ __forceinline__ void cp_wait() {
    asm volatile("cp.async.wait_group %0;" :: "n"(N) : "memory");
}
__device__ __forceinline__ void ldm_x4(uint32_t& r0, uint32_t& r1, uint32_t& r2,
                                       uint32_t& r3, uint32_t addr) {
    asm volatile("ldmatrix.sync.aligned.m8n8.x4.shared.b16 {%0,%1,%2,%3}, [%4];"
                 : "=r"(r0), "=r"(r1), "=r"(r2), "=r"(r3) : "r"(addr));
}
__device__ __forceinline__ void ldm_x4t(uint32_t& r0, uint32_t& r1, uint32_t& r2,
                                        uint32_t& r3, uint32_t addr) {
    asm volatile("ldmatrix.sync.aligned.m8n8.x4.trans.shared.b16 {%0,%1,%2,%3}, [%4];"
                 : "=r"(r0), "=r"(r1), "=r"(r2), "=r"(r3) : "r"(addr));
}
__device__ __forceinline__ void mma_f16(float* c, const uint32_t* a, const uint32_t* b) {
    asm volatile(
        "mma.sync.aligned.m16n8k16.row.col.f32.f16.f16.f32 "
        "{%0,%1,%2,%3}, {%4,%5,%6,%7}, {%8,%9}, {%0,%1,%2,%3};"
        : "+f"(c[0]), "+f"(c[1]), "+f"(c[2]), "+f"(c[3])
        : "r"(a[0]), "r"(a[1]), "r"(a[2]), "r"(a[3]), "r"(b[0]), "r"(b[1]));
}

// =====================================================================
// fp16 mma.sync GEMM: CTA tile 256x128, K=1024, BK=64 halves, 2-stage
// cp.async. mode 0: scatter to q/k/v/g with fused gate scaling (and fp16
// copies of q,k,v). mode 1: plain write to dq ([*,1024]).
// =====================================================================
#define HST 72
#define STAGE_H (384 * HST)
#define GEMM_SMEM (2 * STAGE_H * 2)          // 110592 B

__global__ void __launch_bounds__(256)
gemm_mma_kernel(const __half* __restrict__ Amat, const __half* __restrict__ Bmat,
                float* __restrict__ dq, float* __restrict__ dkk,
                float* __restrict__ dvv, float* __restrict__ dgg, int mode)
{
    extern __shared__ __half smh[];
    const uint32_t sb = smem_u32(smh);
    const int tid = threadIdx.x;
    const int wid = tid >> 5, lane = tid & 31;
    const int m0 = blockIdx.y * 256;
    const int n0 = blockIdx.x * 128;

    const int warpM0 = (wid >> 1) * 64;
    const int warpN0 = (wid & 1) * 64;

    const int aRow  = warpM0 + (lane & 15);
    const int aColH = (lane >> 4) << 3;
    const int bRow  = warpN0 + (lane & 7) + ((lane >> 4) << 3);
    const int bColH = ((lane >> 3) & 1) << 3;

    float c[4][8][4];
    #pragma unroll
    for (int mt = 0; mt < 4; mt++)
        #pragma unroll
        for (int nt = 0; nt < 8; nt++)
            #pragma unroll
            for (int e = 0; e < 4; e++) c[mt][nt][e] = 0.f;

    auto issue = [&](int kt, int s) {
        const uint32_t sS = sb + s * STAGE_H * 2;
        #pragma unroll
        for (int i = 0; i < 12; i++) {
            const int ck = tid + 256 * i;
            const int row = ck >> 3, j = ck & 7;
            const int gc = kt * 64 + j * 8;
            const __half* src = (row < 256)
                ? &Amat[(long)(m0 + row) * DD + gc]
                : &Bmat[(long)(n0 + row - 256) * DD + gc];
            cp16(sS + 2 * (row * HST + j * 8), src);
        }
        cp_commit();
    };

    issue(0, 0);

    for (int it = 0; it < 16; it++) {
        if (it + 1 < 16) { issue(it + 1, (it + 1) & 1); cp_wait<1>(); }
        else             { cp_wait<0>(); }
        __syncthreads();

        const uint32_t sA = sb + (it & 1) * STAGE_H * 2;
        const uint32_t sB = sA + 256 * HST * 2;

        #pragma unroll
        for (int ks = 0; ks < 4; ks++) {
            const int k0 = ks * 16;
            uint32_t a[4][4], b[8][2];
            #pragma unroll
            for (int mt = 0; mt < 4; mt++)
                ldm_x4(a[mt][0], a[mt][1], a[mt][2], a[mt][3],
                       sA + 2 * ((aRow + mt * 16) * HST + k0 + aColH));
            #pragma unroll
            for (int np = 0; np < 4; np++) {
                uint32_t r0, r1, r2, r3;
                ldm_x4(r0, r1, r2, r3,
                       sB + 2 * ((bRow + np * 16) * HST + k0 + bColH));
                b[2 * np][0] = r0;     b[2 * np][1] = r1;
                b[2 * np + 1][0] = r2; b[2 * np + 1][1] = r3;
            }
            #pragma unroll
            for (int mt = 0; mt < 4; mt++)
                #pragma unroll
                for (int nt = 0; nt < 8; nt++)
                    mma_f16(c[mt][nt], a[mt], b[nt]);
        }
        __syncthreads();
    }

    // epilogue: qk codes: 1=q (scale+half copy), 2=k (scale+half copy),
    //           3=v (half copy), 0=g / mode1 (plain)
    float* dst; __half* hdst = nullptr; int ldc, colBase, qk = 0;
    if (mode == 1) { dst = dq; ldc = 1024; colBase = n0; }
    else {
        const int nb = blockIdx.x;
        if (nb < 4)       { dst = dq;  ldc = 512;  colBase = nb * 128; qk = 1; hdst = g_qh; }
        else if (nb < 8)  { dst = dkk; ldc = 512;  colBase = (nb - 4) * 128; qk = 2; hdst = g_kh; }
        else if (nb < 16) { dst = dvv; ldc = 1024; colBase = (nb - 8) * 128; qk = 3; hdst = g_vh; }
        else              { dst = dgg; ldc = 1024; colBase = (nb - 16) * 128; }
    }
    const int rB = m0 + warpM0 + (lane >> 2);
    const int cB = colBase + warpN0 + 2 * (lane & 3);
    #pragma unroll
    for (int mt = 0; mt < 4; mt++)
        #pragma unroll
        for (int nt = 0; nt < 8; nt++) {
            const long r0 = (long)(rB + mt * 16) * ldc + cB + nt * 8;
            const long r1 = (long)(rB + mt * 16 + 8) * ldc + cB + nt * 8;
            float2 v0 = make_float2(c[mt][nt][0], c[mt][nt][1]);
            float2 v1 = make_float2(c[mt][nt][2], c[mt][nt][3]);
            if (qk == 1) {
                float2 Ga = *(const float2*)&g_G[r0];
                float2 Gb = *(const float2*)&g_G[r1];
                v0.x *= expf(Ga.x) * SCALE;  v0.y *= expf(Ga.y) * SCALE;
                v1.x *= expf(Gb.x) * SCALE;  v1.y *= expf(Gb.y) * SCALE;
            } else if (qk == 2) {
                float2 Ga = *(const float2*)&g_G[r0];
                float2 Gb = *(const float2*)&g_G[r1];
                v0.x *= expf(-Ga.x);  v0.y *= expf(-Ga.y);
                v1.x *= expf(-Gb.x);  v1.y *= expf(-Gb.y);
            }
            *(float2*)&dst[r0] = v0;
            *(float2*)&dst[r1] = v1;
            if (qk) {
                *(__half2*)&hdst[r0] = __floats2half2_rn(v0.x, v0.y);
                *(__half2*)&hdst[r1] = __floats2half2_rn(v1.x, v1.y);
            }
        }
}

// =====================================================================
// ONE prep kernel: all 5 weight transposes (fp16 out) AND x -> fp16.
// =====================================================================
__global__ void __launch_bounds__(256) prep_kernel(
    const float* __restrict__ Wq, const float* __restrict__ Wk,
    const float* __restrict__ Wv, const float* __restrict__ Wg,
    const float* __restrict__ Wo, const float* __restrict__ x)
{
    const int bx = blockIdx.x;
    if (bx >= 128) {
        const long base = ((long)(bx - 128) * 32 + blockIdx.y) * 1024 + threadIdx.x * 4;
        float4 v = *(const float4*)&x[base];
        *(__half2*)&g_xh[base]     = __floats2half2_rn(v.x, v.y);
        *(__half2*)&g_xh[base + 2] = __floats2half2_rn(v.z, v.w);
        return;
    }
    __shared__ float t[32][33];
    const float* W; __half* dst; int N, n0;
    if (bx < 16)      { W = Wq; dst = g_WTh;             N = 512;  n0 = bx * 32; }
    else if (bx < 32) { W = Wk; dst = g_WTh + 512 * DD;  N = 512;  n0 = (bx - 16) * 32; }
    else if (bx < 64) { W = Wv; dst = g_WTh + 1024 * DD; N = 1024; n0 = (bx - 32) * 32; }
    else if (bx < 96) { W = Wg; dst = g_WTh + 2048 * DD; N = 1024; n0 = (bx - 64) * 32; }
    else              { W = Wo; dst = g_WoTh;            N = 1024; n0 = (bx - 96) * 32; }

    const int tx = threadIdx.x & 31, ty = threadIdx.x >> 5;
    const int k0 = blockIdx.y * 32;
    #pragma unroll
    for (int i = 0; i < 4; i++)
        t[ty + 8 * i][tx] = W[(long)(k0 + ty + 8 * i) * N + n0 + tx];
    __syncthreads();
    #pragma unroll
    for (int i = 0; i < 4; i++)
        dst[(long)(n0 + ty + 8 * i) * DD + k0 + tx] = __float2half_rn(t[tx][ty + 8 * i]);
}

// =====================================================================
// gate fused: t16 = x@Wgk1 (per chunk, in smem), then
// gk = log_sigmoid(t16@Wgk2 + b)/16 and per-chunk cumsum -> g_G.
// grid = B*NC (64), block = 512. W1 staged in smem.
// =====================================================================
#define GF_SMEM ((DD * LR + CHUNK * LR) * 4)   // 69632 B
__global__ void __launch_bounds__(512) gatefused_kernel(
    const float* __restrict__ x,  const float* __restrict__ W1,
    const float* __restrict__ W2, const float* __restrict__ bias)
{
    extern __shared__ float gfs[];
    float* w1s  = gfs;                 // 1024*16
    float* t16s = gfs + DD * LR;       // 64*16

    const int tid = threadIdx.x;
    const int blk = blockIdx.x;
    const int b = blk >> 5, n = blk & 31;
    const int t0 = b * TT + n * CHUNK;

    for (int i = tid * 4; i < DD * LR; i += 2048)
        *(float4*)&w1s[i] = *(const float4*)&W1[i];
    __syncthreads();

    // phase A: t16 rows. thread = (c = tid>>3, j = tid&7); k-segment j*128
    {
        const int c = tid >> 3, j = tid & 7;
        const float* xr = &x[(long)(t0 + c) * DD + j * 128];
        const float* wb = &w1s[(j * 128) * LR];
        float p[LR];
        #pragma unroll
        for (int r = 0; r < LR; r++) p[r] = 0.f;
        for (int kk = 0; kk < 128; kk++) {
            float xv = xr[kk];
            const float4* w = (const float4*)&wb[kk * LR];
            float4 w0 = w[0], w1 = w[1], w2 = w[2], w3 = w[3];
            p[0]  += xv * w0.x;  p[1]  += xv * w0.y;
            p[2]  += xv * w0.z;  p[3]  += xv * w0.w;
            p[4]  += xv * w1.x;  p[5]  += xv * w1.y;
            p[6]  += xv * w1.z;  p[7]  += xv * w1.w;
            p[8]  += xv * w2.x;  p[9]  += xv * w2.y;
            p[10] += xv * w2.z;  p[11] += xv * w2.w;
            p[12] += xv * w3.x;  p[13] += xv * w3.y;
            p[14] += xv * w3.z;  p[15] += xv * w3.w;
        }
        #pragma unroll
        for (int off = 4; off; off >>= 1)
            #pragma unroll
            for (int r = 0; r < LR; r++)
                p[r] += __shfl_xor_sync(0xffffffffu, p[r], off);
        if (j == 0)
            #pragma unroll
            for (int r = 0; r < LR; r++) t16s[c * LR + r] = p[r];
    }
    __syncthreads();

    // phase B: logsig + cumsum, kd = tid
    const int kd = tid;
    float w[LR];
    #pragma unroll
    for (int r = 0; r < LR; r++) w[r] = W2[r * KDIM + kd];
    const float bs = bias[kd];

    float run = 0.f;
    for (int c = 0; c < CHUNK; c++) {
        float s = bs;
        #pragma unroll
        for (int r = 0; r < LR; r++) s += t16s[c * LR + r] * w[r];
        float ls = fminf(s, 0.f) - __logf(1.f + __expf(-fabsf(s)));
        run += ls * (1.f / 16.f);
        g_G[(long)(t0 + c) * KDIM + kd] = run;
    }
}

// =====================================================================
// Sequential inter-chunk scan (fp32; launch #4 -> profiled).
// =====================================================================
#define SC_S    0
#define SC_QG   2176
#define SC_KGT  (2176 + 8192)
#define SC_V    (2176 + 8192 + 8704)
#define SC_EGL  (2176 + 8192 + 8704 + 1088)
#define SCAN_SMEM_BYTES ((2176 + 8192 + 8704 + 1088 + 128) * 4)
__global__ void __launch_bounds__(256) scan_kernel()
{
    extern __shared__ float sm[];
    float* S   = sm + SC_S;     // 128*17
    float* qgS = sm + SC_QG;    // 64*128
    float* kgT = sm + SC_KGT;   // 128*68
    float* v_s = sm + SC_V;     // 64*17
    float* eGl = sm + SC_EGL;   // 128

    const int blk = blockIdx.x;
    const int vs = blk & 15, h = (blk >> 4) & 3, b = blk >> 6;
    const int tid = threadIdx.x;
    const int vi = tid & 15, grp = tid >> 4;
    const int colK = h * DK;
    const int colV = h * DV + vs * 16;

    for (int i = tid; i < 2176; i += 256) S[i] = 0.f;

    for (int n = 0; n < NC; n++) {
        const int t0 = b * TT + n * CHUNK;
        __syncthreads();
        if (tid < 128)
            eGl[tid] = expf(g_G[(long)(t0 + 63) * KDIM + colK + tid]);
        #pragma unroll 4
        for (int it = 0; it < 32; it++) {
            int idx = tid + 256 * it;
            int c = idx >> 7, dk = idx & 127;
            long gidx = (long)(t0 + c) * KDIM + colK + dk;
            qgS[idx] = g_q[gidx];
            kgT[dk * 68 + c] = g_k[gidx];
        }
        #pragma unroll
        for (int it = 0; it < 4; it++) {
            int idx = tid + 256 * it;
            int c = idx >> 4, u = idx & 15;
            v_s[c * 17 + u] = g_v[(long)(t0 + c) * VDIM + colV + u];
        }
        __syncthreads();

        {
            const int c0 = grp * 4;
            float a0 = 0.f, a1 = 0.f, a2 = 0.f, a3 = 0.f;
            for (int k4 = 0; k4 < 128; k4 += 4) {
                float s0 = S[(k4 + 0) * 17 + vi];
                float s1 = S[(k4 + 1) * 17 + vi];
                float s2 = S[(k4 + 2) * 17 + vi];
                float s3 = S[(k4 + 3) * 17 + vi];
                float4 q0 = *(const float4*)&qgS[(c0 + 0) * 128 + k4];
                float4 q1 = *(const float4*)&qgS[(c0 + 1) * 128 + k4];
                float4 q2 = *(const float4*)&qgS[(c0 + 2) * 128 + k4];
                float4 q3 = *(const float4*)&qgS[(c0 + 3) * 128 + k4];
                a0 += q0.x * s0 + q0.y * s1 + q0.z * s2 + q0.w * s3;
                a1 += q1.x * s0 + q1.y * s1 + q1.z * s2 + q1.w * s3;
                a2 += q2.x * s0 + q2.y * s1 + q2.z * s2 + q2.w * s3;
                a3 += q3.x * s0 + q3.y * s1 + q3.z * s2 + q3.w * s3;
            }
            g_o[(long)(t0 + c0 + 0) * VDIM + colV + vi] = a0;
            g_o[(long)(t0 + c0 + 1) * VDIM + colV + vi] = a1;
            g_o[(long)(t0 + c0 + 2) * VDIM + colV + vi] = a2;
            g_o[(long)(t0 + c0 + 3) * VDIM + colV + vi] = a3;
        }
        __syncthreads();

        {
            const int k0 = grp * 8;
            float u0 = 0.f, u1 = 0.f, u2 = 0.f, u3 = 0.f;
            float u4 = 0.f, u5 = 0.f, u6 = 0.f, u7 = 0.f;
            for (int c4 = 0; c4 < 64; c4 += 4) {
                float v0 = v_s[(c4 + 0) * 17 + vi];
                float v1 = v_s[(c4 + 1) * 17 + vi];
                float v2 = v_s[(c4 + 2) * 17 + vi];
                float v3 = v_s[(c4 + 3) * 17 + vi];
                float4 kv;
                kv = *(const float4*)&kgT[(k0 + 0) * 68 + c4];
                u0 += kv.x * v0 + kv.y * v1 + kv.z * v2 + kv.w * v3;
                kv = *(const float4*)&kgT[(k0 + 1) * 68 + c4];
                u1 += kv.x * v0 + kv.y * v1 + kv.z * v2 + kv.w * v3;
                kv = *(const float4*)&kgT[(k0 + 2) * 68 + c4];
                u2 += kv.x * v0 + kv.y * v1 + kv.z * v2 + kv.w * v3;
                kv = *(const float4*)&kgT[(k0 + 3) * 68 + c4];
                u3 += kv.x * v0 + kv.y * v1 + kv.z * v2 + kv.w * v3;
                kv = *(const float4*)&kgT[(k0 + 4) * 68 + c4];
                u4 += kv.x * v0 + kv.y * v1 + kv.z * v2 + kv.w * v3;
                kv = *(const float4*)&kgT[(k0 + 5) * 68 + c4];
                u5 += kv.x * v0 + kv.y * v1 + kv.z * v2 + kv.w * v3;
                kv = *(const float4*)&kgT[(k0 + 6) * 68 + c4];
                u6 += kv.x * v0 + kv.y * v1 + kv.z * v2 + kv.w * v3;
                kv = *(const float4*)&kgT[(k0 + 7) * 68 + c4];
                u7 += kv.x * v0 + kv.y * v1 + kv.z * v2 + kv.w * v3;
            }
            S[(k0 + 0) * 17 + vi] = eGl[k0 + 0] * (S[(k0 + 0) * 17 + vi] + u0);
            S[(k0 + 1) * 17 + vi] = eGl[k0 + 1] * (S[(k0 + 1) * 17 + vi] + u1);
            S[(k0 + 2) * 17 + vi] = eGl[k0 + 2] * (S[(k0 + 2) * 17 + vi] + u2);
            S[(k0 + 3) * 17 + vi] = eGl[k0 + 3] * (S[(k0 + 3) * 17 + vi] + u3);
            S[(k0 + 4) * 17 + vi] = eGl[k0 + 4] * (S[(k0 + 4) * 17 + vi] + u4);
            S[(k0 + 5) * 17 + vi] = eGl[k0 + 5] * (S[(k0 + 5) * 17 + vi] + u5);
            S[(k0 + 6) * 17 + vi] = eGl[k0 + 6] * (S[(k0 + 6) * 17 + vi] + u6);
            S[(k0 + 7) * 17 + vi] = eGl[k0 + 7] * (S[(k0 + 7) * 17 + vi] + u7);
        }
    }
}

// =====================================================================
// Intra-chunk attention via fp16 mma:
//   A = tril(qg @ kg^T) [64x64x128], then o += A @ v [64x256x64]
// grid = 256 blocks (b,h,n), 256 threads (8 warps = 4(M) x 2(N)).
// =====================================================================
#define IQ_ST 136                   // qh/kh row stride (halves)
#define IA_ST 72                    // A row stride
#define IV_ST 264                   // v row stride
#define IN_QH 0
#define IN_KH (64 * IQ_ST)          // 8704
#define IN_A  (2 * 64 * IQ_ST)     // 17408
#define IN_V  (IN_A + 64 * IA_ST)  // 22016
#define INTRA_SMEM_BYTES ((IN_V + 64 * IV_ST) * 2)   // 77824 B

__global__ void __launch_bounds__(256) intra_kernel()
{
    extern __shared__ __half ish[];
    const uint32_t sb = smem_u32(ish);
    const int blk = blockIdx.x;
    const int n = blk & 31, h = (blk >> 5) & 3, b = blk >> 7;
    const int tid = threadIdx.x;
    const int wid = tid >> 5, lane = tid & 31;
    const int t0 = b * TT + n * CHUNK;
    const int colK = h * DK;
    const int colV = h * DV;

    const int wr = wid >> 1;        // 0..3  (M)
    const int wc = wid & 1;         // 0..1  (N)

    // ---- stage qh, kh (64x128 halves each) and vh (64x256 halves) ----
    #pragma unroll
    for (int i = 0; i < 8; i++) {                 // qh/kh: 2048 chunks
        const int ck = tid + 256 * i;
        const int mat = ck >> 10, rem = ck & 1023;
        const int row = rem >> 4, ch = rem & 15;
        const __half* src = (mat ? g_kh : g_qh) + (long)(t0 + row) * KDIM + colK + ch * 8;
        cp16(sb + 2 * ((mat ? IN_KH : IN_QH) + row * IQ_ST + ch * 8), src);
    }
    #pragma unroll
    for (int i = 0; i < 8; i++) {                 // vh: 2048 chunks
        const int ck = tid + 256 * i;
        const int row = ck >> 5, ch = ck & 31;
        cp16(sb + 2 * (IN_V + row * IV_ST + ch * 8),
             g_vh + (long)(t0 + row) * VDIM + colV + ch * 8);
    }
    cp_commit();
    cp_wait<0>();
    __syncthreads();

    // ---- mma 1: A[64x64] = qg @ kg^T, warp tile 16x32, K=128 ----
    {
        const int aRow  = wr * 16 + (lane & 15);
        const int aColH = (lane >> 4) << 3;
        const int bRow  = wc * 32 + (lane & 7) + ((lane >> 4) << 3);
        const int bColH = ((lane >> 3) & 1) << 3;

        float acc[4][4];
        #pragma unroll
        for (int nt = 0; nt < 4; nt++)
            #pragma unroll
            for (int e = 0; e < 4; e++) acc[nt][e] = 0.f;

        #pragma unroll
        for (int ks = 0; ks < 8; ks++) {
            const int k0 = ks * 16;
            uint32_t a[4], bfr[4][2];
            ldm_x4(a[0], a[1], a[2], a[3],
                   sb + 2 * (IN_QH + aRow * IQ_ST + k0 + aColH));
            #pragma unroll
            for (int np = 0; np < 2; np++) {
                uint32_t r0, r1, r2, r3;
                ldm_x4(r0, r1, r2, r3,
                       sb + 2 * (IN_KH + (bRow + np * 16) * IQ_ST + k0 + bColH));
                bfr[2 * np][0] = r0;     bfr[2 * np][1] = r1;
                bfr[2 * np + 1][0] = r2; bfr[2 * np + 1][1] = r3;
            }
            #pragma unroll
            for (int nt = 0; nt < 4; nt++)
                mma_f16(acc[nt], a, bfr[nt]);
        }

        // tril mask + fp16 store to A smem
        const int row0 = wr * 16 + (lane >> 2);
        #pragma unroll
        for (int nt = 0; nt < 4; nt++) {
            const int col0 = wc * 32 + nt * 8 + 2 * (lane & 3);
            float m0 = (col0     <= row0) ? acc[nt][0] : 0.f;
            float m1 = (col0 + 1 <= row0) ? acc[nt][1] : 0.f;
            float m2 = (col0     <= row0 + 8) ? acc[nt][2] : 0.f;
            float m3 = (col0 + 1 <= row0 + 8) ? acc[nt][3] : 0.f;
            *(__half2*)&ish[IN_A + row0 * IA_ST + col0]       = __floats2half2_rn(m0, m1);
            *(__half2*)&ish[IN_A + (row0 + 8) * IA_ST + col0] = __floats2half2_rn(m2, m3);
        }
    }
    __syncthreads();

    // ---- mma 2: O[64x256] += A @ v, warp tile 16x128, K=64 ----
    {
        const int aRow  = wr * 16 + (lane & 15);
        const int aColH = (lane >> 4) << 3;
        const int vRow  = (lane & 15);                // k index within step
        const int vColH = (lane >> 4) << 3;           // n offset 0/8

        float acc[16][4];
        #pragma unroll
        for (int nt = 0; nt < 16; nt++)
            #pragma unroll
            for (int e = 0; e < 4; e++) acc[nt][e] = 0.f;

        #pragma unroll
        for (int ks = 0; ks < 4; ks++) {
            const int k0 = ks * 16;
            uint32_t a[4], bfr[16][2];
            ldm_x4(a[0], a[1], a[2], a[3],
                   sb + 2 * (IN_A + aRow * IA_ST + k0 + aColH));
            #pragma unroll
            for (int nn = 0; nn < 8; nn++) {
                const int u0 = wc * 128 + nn * 16;
                uint32_t r0, r1, r2, r3;
                ldm_x4t(r0, r1, r2, r3,
                        sb + 2 * (IN_V + (k0 + vRow) * IV_ST + u0 + vColH));
                bfr[2 * nn][0] = r0;     bfr[2 * nn][1] = r1;
                bfr[2 * nn + 1][0] = r2; bfr[2 * nn + 1][1] = r3;
            }
            #pragma unroll
            for (int nt = 0; nt < 16; nt++)
                mma_f16(acc[nt], a, bfr[nt]);
        }

        // accumulate into g_o
        const int row0 = t0 + wr * 16 + (lane >> 2);
        #pragma unroll
        for (int nt = 0; nt < 16; nt++) {
            const int col = colV + wc * 128 + nt * 8 + 2 * (lane & 3);
            float2* p0 = (float2*)&g_o[(long)row0 * VDIM + col];
            float2* p1 = (float2*)&g_o[(long)(row0 + 8) * VDIM + col];
            float2 c0 = *p0, c1 = *p1;
            c0.x += acc[nt][0]; c0.y += acc[nt][1];
            c1.x += acc[nt][2]; c1.y += acc[nt][3];
            *p0 = c0; *p1 = c1;
        }
    }
}

// =====================================================================
// Per-head RMS norm + SiLU gate — one warp per head-row; writes fp16.
// =====================================================================
__global__ void __launch_bounds__(256) norm_gate_kernel(const float* __restrict__ gnw)
{
    const int idx = blockIdx.x * 8 + (threadIdx.x >> 5);
    const int lane = threadIdx.x & 31;
    const long base = (long)idx * DV + lane * 8;

    float4 x0 = *(const float4*)&g_o[base];
    float4 x1 = *(const float4*)&g_o[base + 4];
    float ss = x0.x*x0.x + x0.y*x0.y + x0.z*x0.z + x0.w*x0.w
             + x1.x*x1.x + x1.y*x1.y + x1.z*x1.z + x1.w*x1.w;
    #pragma unroll
    for (int off = 16; off; off >>= 1)
        ss += __shfl_xor_sync(0xffffffffu, ss, off);

    const float rr = rsqrtf(ss * (1.f / 256.f) + EPSN);
    float4 g0 = *(const float4*)&g_g[base];
    float4 g1 = *(const float4*)&g_g[base + 4];
    float4 w0 = *(const float4*)&gnw[lane * 8];
    float4 w1 = *(const float4*)&gnw[lane * 8 + 4];

    float o0 = x0.x * rr * w0.x * (g0.x / (1.f + expf(-g0.x)));
    float o1 = x0.y * rr * w0.y * (g0.y / (1.f + expf(-g0.y)));
    float o2 = x0.z * rr * w0.z * (g0.z / (1.f + expf(-g0.z)));
    float o3 = x0.w * rr * w0.w * (g0.w / (1.f + expf(-g0.w)));
    float o4 = x1.x * rr * w1.x * (g1.x / (1.f + expf(-g1.x)));
    float o5 = x1.y * rr * w1.y * (g1.y / (1.f + expf(-g1.y)));
    float o6 = x1.z * rr * w1.z * (g1.z / (1.f + expf(-g1.z)));
    float o7 = x1.w * rr * w1.w * (g1.w / (1.f + expf(-g1.w)));

    *(__half2*)&g_oh[base]     = __floats2half2_rn(o0, o1);
    *(__half2*)&g_oh[base + 2] = __floats2half2_rn(o2, o3);
    *(__half2*)&g_oh[base + 4] = __floats2half2_rn(o4, o5);
    *(__half2*)&g_oh[base + 6] = __floats2half2_rn(o6, o7);
}

// =====================================================================
// launch  (4th launch = scan -> that's what ncu captures this round)
// =====================================================================
extern "C" void kernel_launch(void* const* d_in, const int* in_sizes, int n_in,
                              void* d_out, int out_size)
{
    const float* x    = (const float*)d_in[0];
    const float* Wq   = (const float*)d_in[1];
    const float* Wk   = (const float*)d_in[2];
    const float* Wv   = (const float*)d_in[3];
    const float* Wg   = (const float*)d_in[4];
    const float* Wgk1 = (const float*)d_in[5];
    const float* Wgk2 = (const float*)d_in[6];
    const float* bgk2 = (const float*)d_in[7];
    const float* gnw  = (const float*)d_in[8];
    const float* Wo   = (const float*)d_in[9];
    float* out = (float*)d_out;

    float *q, *k, *v, *g;
    __half *xh, *WTh, *WoTh, *oh;
    cudaGetSymbolAddress((void**)&q,    g_q);
    cudaGetSymbolAddress((void**)&k,    g_k);
    cudaGetSymbolAddress((void**)&v,    g_v);
    cudaGetSymbolAddress((void**)&g,    g_g);
    cudaGetSymbolAddress((void**)&xh,   g_xh);
    cudaGetSymbolAddress((void**)&WTh,  g_WTh);
    cudaGetSymbolAddress((void**)&WoTh, g_WoTh);
    cudaGetSymbolAddress((void**)&oh,   g_oh);

    cudaFuncSetAttribute(scan_kernel,      cudaFuncAttributeMaxDynamicSharedMemorySize, SCAN_SMEM_BYTES);
    cudaFuncSetAttribute(intra_kernel,     cudaFuncAttributeMaxDynamicSharedMemorySize, INTRA_SMEM_BYTES);
    cudaFuncSetAttribute(gemm_mma_kernel,  cudaFuncAttributeMaxDynamicSharedMemorySize, GEMM_SMEM);
    cudaFuncSetAttribute(gatefused_kernel, cudaFuncAttributeMaxDynamicSharedMemorySize, GF_SMEM);

    // 1: weight transposes + x conversion
    prep_kernel<<<dim3(256, 32), 256>>>(Wq, Wk, Wv, Wg, Wo, x);            // 1

    // 2: fused gate path (t16 + logsig + cumsum)
    gatefused_kernel<<<BB * NC, 512, GF_SMEM>>>(x, Wgk1, Wgk2, bgk2);      // 2

    // 3: fused q/k/v/g projection GEMM with gate scaling epilogue
    gemm_mma_kernel<<<dim3(24, 16), 256, GEMM_SMEM>>>(xh, WTh, q, k, v, g, 0);  // 3

    // 4: scan (profiled this round)
    scan_kernel<<<BB * HH * 16, 256, SCAN_SMEM_BYTES>>>();                 // 4

    // 5: intra-chunk attention (fp16 mma)
    intra_kernel<<<NC * BB * HH, 256, INTRA_SMEM_BYTES>>>();               // 5

    // 6-7: norm/gate + output projection
    norm_gate_kernel<<<BT * HH / 8, 256>>>(gnw);                           // 6
    gemm_mma_kernel<<<dim3(8, 16), 256, GEMM_SMEM>>>(oh, WoTh, out, nullptr, nullptr, nullptr, 1);  // 7
}